// round 16
// baseline (speedup 1.0000x reference)
#include <cuda_runtime.h>
#include <cuda_fp16.h>
#include <math.h>
#include <stdint.h>

#define Bq 512
#define Wq 40
#define Vq 12000
#define Eq 512
#define Hq 512
#define G4 2048   // 4*H
#define R_NCTA 256

// ---------------- scratch (device globals; no allocation) ----------------
__device__ __half g_table[(size_t)Vq * Eq];       // half tanh(lut^T)
__device__ __half g_hseq_h[Bq * Wq * 2 * Hq];     // layer-0 output (half)
__device__ __half g_ha[2][2 * Bq * Hq];           // h ping-pong (layer-1)
__device__ float g_c[2 * Bq * Hq];
__device__ __half g_wr[10485760];                 // half weights: wih0|whh0|wih1|whh1
__device__ unsigned g_gbar[2 * 32 * Wq];          // group barriers [layer][group][step]

#define OFF_WIH0 0
#define OFF_WHH0 2097152
#define OFF_WIH1 4194304
#define OFF_WHH1 8388608
#define W_TOTAL  10485760

__device__ __forceinline__ float sig_fast(float x) {
    return __fdividef(1.0f, 1.0f + __expf(-x));
}
__device__ __forceinline__ float tanh_fast(float x) {
    return 2.0f * __fdividef(1.0f, 1.0f + __expf(-2.0f * x)) - 1.0f;
}
__device__ __forceinline__ void cp16(uint32_t dst, const void* src) {
    asm volatile("cp.async.cg.shared.global [%0], [%1], 16;" :: "r"(dst), "l"(src));
}
__device__ __forceinline__ void cp16z(uint32_t dst, const void* src, int sz) {
    asm volatile("cp.async.cg.shared.global [%0], [%1], 16, %2;"
                 :: "r"(dst), "l"(src), "r"(sz));
}
#define LDSM_X4(r0, r1, r2, r3, addr) \
    asm volatile("ldmatrix.sync.aligned.m8n8.x4.shared.b16 {%0,%1,%2,%3}, [%4];" \
                 : "=r"(r0), "=r"(r1), "=r"(r2), "=r"(r3) : "r"(addr))
#define MMA16816(acc, a0, a1, a2, a3, b0, b1) \
    asm volatile( \
        "mma.sync.aligned.m16n8k16.row.col.f32.f16.f16.f32 " \
        "{%0,%1,%2,%3}, {%4,%5,%6,%7}, {%8,%9}, {%0,%1,%2,%3};" \
        : "+f"((acc)[0]), "+f"((acc)[1]), "+f"((acc)[2]), "+f"((acc)[3]) \
        : "r"(a0), "r"(a1), "r"(a2), "r"(a3), "r"(b0), "r"(b1))

// ---------------- one-time: all weights -> half, zero barriers (fused) ----------
__global__ void cvt_all_weights_kernel(const float* __restrict__ w0, const float* __restrict__ w1,
                                       const float* __restrict__ w2, const float* __restrict__ w3) {
    int i = blockIdx.x * blockDim.x + threadIdx.x;
    if (i < 2 * 32 * Wq) g_gbar[i] = 0;
    int idx4 = i * 4;
    if (idx4 >= W_TOTAL) return;
    const float* src; int off;
    if (idx4 < OFF_WHH0)      { src = w0; off = idx4; }
    else if (idx4 < OFF_WIH1) { src = w1; off = idx4 - OFF_WHH0; }
    else if (idx4 < OFF_WHH1) { src = w2; off = idx4 - OFF_WIH1; }
    else                      { src = w3; off = idx4 - OFF_WHH1; }
    float4 v = *(const float4*)(src + off);
    __half2 a = __floats2half2_rn(v.x, v.y);
    __half2 b = __floats2half2_rn(v.z, v.w);
    __half2* dst = (__half2*)&g_wr[idx4];
    dst[0] = a; dst[1] = b;
}

// ---------------- tanh + transpose lookup: g_table[v][e] = h(tanh(lut[e][v])) ----
__global__ void tanh_transpose_kernel(const float* __restrict__ lut) {
    __shared__ float tile[32][33];
    int v0 = blockIdx.x * 32;
    int e0 = blockIdx.y * 32;
    int tx = threadIdx.x, ty = threadIdx.y;
#pragma unroll
    for (int i = ty; i < 32; i += 8) {
        int e = e0 + i, v = v0 + tx;
        tile[i][tx] = (v < Vq) ? lut[(size_t)e * Vq + v] : 0.0f;
    }
    __syncthreads();
#pragma unroll
    for (int i = ty; i < 32; i += 8) {
        int v = v0 + i, e = e0 + tx;
        if (v < Vq) g_table[(size_t)v * Eq + e] = __float2half_rn(tanhf(tile[tx][i]));
    }
}

// ---------------- fully fused persistent LSTM layer -----------------------------
// 256 CTAs (2/SM): CTA = (dir, 64 b-rows, 32 h-cols).
// Per step: gates GEMM (h_prev @ whh^T) -> fused gate epilogue (xg from smem
// xbuf) -> h write -> arrive -> xg GEMM for t+1 (x @ wih^T + bias, barrier-
// independent; fills the skew window) -> prefetch gates B -> wait.
// LAYER0: x rows gathered from g_table via ques (zero rows for v==0), h -> hseq_h.
// LAYER0=0: x rows from hseq_h (K=1024), h -> g_ha ping-pong, final h -> out.
#define F_ASZ (64 * 36)         // u32
#define F_BSZ (128 * 36)        // u32
#define F_A0  (2 * F_BSZ)
#define F_B2  (2 * F_BSZ + 3 * F_ASZ)
#define F_XB  (3 * F_BSZ + 3 * F_ASZ)       // 20736 u32
#define F_SMEM ((F_XB + 4224) * 4)          // + xbuf 64x132 halves = 99840 B
#define GSM_STRIDE 130
#define XB_STRIDE 132
template <int LAYER0>
__global__ __launch_bounds__(256, 2) void lstm_fused(
    const __half* __restrict__ whh,      // [2][G4][Hq]
    const __half* __restrict__ wih,      // [2][G4][K_X]
    const float* __restrict__ bias,      // (2,2,G4)
    const int* __restrict__ ques,
    const int* __restrict__ qlen,
    float* __restrict__ out,
    int bar_ofs)
{
    const int K_X = LAYER0 ? Eq : 2 * Hq;
    const int NCHX = K_X / 64;

    extern __shared__ uint32_t sm[];
    float* gsm = (float*)(sm + F_A0);     // [64][130] aliases A0..B2
    __half* xbuf = (__half*)(sm + F_XB);  // [64][132] dedicated
    uint32_t base = (uint32_t)__cvta_generic_to_shared(sm);

    int tid = threadIdx.x;
    int bx = blockIdx.x;
    int dir = bx >> 7;
    int r = bx & 127;
    int m0 = (r >> 4) * 64;
    int ht0 = (r & 15) * 32;
    int grp = bx >> 4;

    int wid = tid >> 5, lane = tid & 31;
    int wm = wid >> 2, wn = wid & 3;      // warp tile: 32 m x 32 n (gate wn)
    int gid = lane >> 2, tg = lane & 3;

    int lrow = (lane & 7) + ((lane >> 3) & 1) * 8;
    int lk = (lane >> 4) * 4;
    uint32_t aLane = base + (uint32_t)(((wm * 32 + lrow) * 36 + lk) * 4);
    uint32_t bLane = base + (uint32_t)(((wn * 32 + lrow) * 36 + lk) * 4);

    const __half* whbase = whh + (size_t)dir * G4 * Hq;
    const __half* wxbase = wih + (size_t)dir * G4 * K_X;

    // per-thread bias pairs for xbuf write: col nc = wn*32 + nt*8 + tg*2
    float2 biasv[4];
    {
        const float* bp = bias + (size_t)dir * 2 * G4;
#pragma unroll
        for (int nt = 0; nt < 4; nt++) {
            int n = wn * 512 + ht0 + nt * 8 + tg * 2;
            biasv[nt].x = bp[n] + bp[G4 + n];
            biasv[nt].y = bp[n + 1] + bp[G4 + n + 1];
        }
    }

    auto aStage = [&](int s) -> uint32_t { return (uint32_t)((F_A0 + s * F_ASZ) * 4); };
    auto bStage = [&](int s) -> uint32_t {
        return (uint32_t)((s == 2 ? F_B2 : s * F_BSZ) * 4);
    };

    // ---- gates GEMM loaders (A = h_prev, B = whh strip) ----
    const __half* habase = nullptr;
    size_t rstride = LAYER0 ? (size_t)Wq * 2 * Hq : (size_t)Hq;
    auto load_A = [&](int s, int k0) {
        uint32_t ab = base + aStage(s);
#pragma unroll
        for (int i = 0; i < 2; i++) {
            int c = tid + i * 256;
            int row = c >> 3, seg = c & 7;
            cp16(ab + (uint32_t)((row * 36 + seg * 4) * 4),
                 habase + (size_t)(m0 + row) * rstride + k0 + seg * 8);
        }
        asm volatile("cp.async.commit_group;");
    };
    auto load_Bw = [&](int s, int k0) {
        uint32_t bb = base + bStage(s);
#pragma unroll
        for (int i = 0; i < 4; i++) {
            int c = tid + i * 256;
            int row = c >> 3, seg = c & 7;
            int grow = ((row >> 5) << 9) + ht0 + (row & 31);
            cp16(bb + (uint32_t)((row * 36 + seg * 4) * 4),
                 whbase + (size_t)grow * Hq + k0 + seg * 8);
        }
        asm volatile("cp.async.commit_group;");
    };
    auto load_AB = [&](int s, int k0) {
        load_A(s, k0);  // commits its own group
        uint32_t bb = base + bStage(s);
#pragma unroll
        for (int i = 0; i < 4; i++) {
            int c = tid + i * 256;
            int row = c >> 3, seg = c & 7;
            int grow = ((row >> 5) << 9) + ht0 + (row & 31);
            cp16(bb + (uint32_t)((row * 36 + seg * 4) * 4),
                 whbase + (size_t)grow * Hq + k0 + seg * 8);
        }
        asm volatile("cp.async.commit_group;");
    };

    // ---- xg GEMM per-thread A-row state (set per step) ----
    int rA0 = tid >> 3;                   // 0..31 (i=0) ; +32 for i=1
    int segX = tid & 7;
    const __half* xp0 = nullptr;
    const __half* xp1 = nullptr;
    int xsz0 = 16, xsz1 = 16;
    auto set_xrows = [&](int tn) {
        if (LAYER0) {
            int v0 = ques[(m0 + rA0) * Wq + tn];
            int v1 = ques[(m0 + rA0 + 32) * Wq + tn];
            xp0 = g_table + (size_t)(v0 > 0 ? v0 - 1 : 0) * Eq + segX * 8;
            xp1 = g_table + (size_t)(v1 > 0 ? v1 - 1 : 0) * Eq + segX * 8;
            xsz0 = v0 > 0 ? 16 : 0;
            xsz1 = v1 > 0 ? 16 : 0;
        } else {
            xp0 = g_hseq_h + ((size_t)(m0 + rA0) * Wq + tn) * (2 * Hq) + segX * 8;
            xp1 = g_hseq_h + ((size_t)(m0 + rA0 + 32) * Wq + tn) * (2 * Hq) + segX * 8;
        }
    };
    auto load_X = [&](int s, int k0) {
        uint32_t ab = base + aStage(s);
        cp16z(ab + (uint32_t)((rA0 * 36 + segX * 4) * 4), xp0 + k0, xsz0);
        cp16z(ab + (uint32_t)(((rA0 + 32) * 36 + segX * 4) * 4), xp1 + k0, xsz1);
        uint32_t bb = base + bStage(s);
#pragma unroll
        for (int i = 0; i < 4; i++) {
            int c = tid + i * 256;
            int row = c >> 3, seg = c & 7;
            int grow = ((row >> 5) << 9) + ht0 + (row & 31);
            cp16(bb + (uint32_t)((row * 36 + seg * 4) * 4),
                 wxbase + (size_t)grow * K_X + k0 + seg * 8);
        }
        asm volatile("cp.async.commit_group;");
    };

    auto computeChunk = [&](uint32_t sa, uint32_t sb, float (&A)[2][4][4]) {
#pragma unroll
        for (int g = 0; g < 4; g++) {
            uint32_t kby = g * 32;
            uint32_t af[2][4], bf[4][2];
#pragma unroll
            for (int mt = 0; mt < 2; mt++)
                LDSM_X4(af[mt][0], af[mt][1], af[mt][2], af[mt][3],
                        aLane + sa + (uint32_t)(mt * 16 * 36 * 4) + kby);
#pragma unroll
            for (int p = 0; p < 2; p++)
                LDSM_X4(bf[2 * p][0], bf[2 * p + 1][0], bf[2 * p][1], bf[2 * p + 1][1],
                        bLane + sb + (uint32_t)(p * 16 * 36 * 4) + kby);
#pragma unroll
            for (int mt = 0; mt < 2; mt++)
#pragma unroll
                for (int nt = 0; nt < 4; nt++)
                    MMA16816(A[mt][nt], af[mt][0], af[mt][1], af[mt][2], af[mt][3],
                             bf[nt][0], bf[nt][1]);
        }
    };

    // xg GEMM + xbuf write (bias folded)
    auto xg_gemm = [&](int tn) {
        set_xrows(tn);
        float acc2[2][4][4];
#pragma unroll
        for (int mt = 0; mt < 2; mt++)
#pragma unroll
            for (int nt = 0; nt < 4; nt++)
#pragma unroll
                for (int q = 0; q < 4; q++) acc2[mt][nt][q] = 0.0f;
        load_X(0, 0);
        load_X(1, 64);
        for (int c = 0; c < NCHX; c++) {
            if (c < NCHX - 1) asm volatile("cp.async.wait_group 1;");
            else              asm volatile("cp.async.wait_group 0;");
            __syncthreads();
            if (c + 2 < NCHX) load_X((c + 2) % 3, (c + 2) * 64);
            computeChunk(aStage(c % 3), bStage(c % 3), acc2);
        }
        // write xbuf (+bias)
#pragma unroll
        for (int mt = 0; mt < 2; mt++)
#pragma unroll
            for (int nt = 0; nt < 4; nt++)
#pragma unroll
                for (int rs = 0; rs < 2; rs++) {
                    int mr = wm * 32 + mt * 16 + gid + rs * 8;
                    int nc = wn * 32 + nt * 8 + tg * 2;
                    *(__half2*)&xbuf[mr * XB_STRIDE + nc] = __floats2half2_rn(
                        acc2[mt][nt][rs * 2] + biasv[nt].x,
                        acc2[mt][nt][rs * 2 + 1] + biasv[nt].y);
                }
        __syncthreads();   // stage buffers free; xbuf written
    };

    // ---- pre-loop: xg for t_(0) ----
    xg_gemm(dir ? (Wq - 1) : 0);

    for (int step = 0; step < Wq; step++) {
        int t_ = dir ? (Wq - 1 - step) : step;

        float acc[2][4][4];
#pragma unroll
        for (int mt = 0; mt < 2; mt++)
#pragma unroll
            for (int nt = 0; nt < 4; nt++)
#pragma unroll
                for (int q = 0; q < 4; q++) acc[mt][nt][q] = 0.0f;

        if (step > 0) {
            if (LAYER0) {
                int tprev = dir ? (Wq - step) : (step - 1);
                habase = g_hseq_h + (size_t)tprev * 2 * Hq + dir * Hq;
            } else {
                habase = g_ha[(step - 1) & 1] + dir * Bq * Hq;
            }
            // gates B0,B1 prefetched at end of previous step
            load_A(0, 0);
            load_A(1, 64);
            for (int kc = 0; kc < 8; kc++) {
                if (kc < 7) asm volatile("cp.async.wait_group 1;");
                else        asm volatile("cp.async.wait_group 0;");
                __syncthreads();
                if (kc == 0)      load_AB(2, 128);
                else if (kc <= 5) load_AB((kc + 2) % 3, (kc + 2) * 64);
                computeChunk(aStage(kc % 3), bStage(kc % 3), acc);
            }
        }

        // ---- stage gates into gsm (aliases stages; xg/gate reads all done) ----
        __syncthreads();
#pragma unroll
        for (int mt = 0; mt < 2; mt++)
#pragma unroll
            for (int nt = 0; nt < 4; nt++)
#pragma unroll
                for (int rs = 0; rs < 2; rs++) {
                    int mr = wm * 32 + mt * 16 + gid + rs * 8;
                    int nc = wn * 32 + nt * 8 + tg * 2;
                    float2 v;
                    v.x = acc[mt][nt][rs * 2];
                    v.y = acc[mt][nt][rs * 2 + 1];
                    *(float2*)&gsm[mr * GSM_STRIDE + nc] = v;
                }
        __syncthreads();

        // ---- fused gate epilogue (xg from xbuf) ----
        __half* haw = LAYER0 ? nullptr : (g_ha[step & 1] + dir * Bq * Hq);
        int hl = (tid & 15) * 2;
        int rb = tid >> 4;
#pragma unroll
        for (int it = 0; it < 4; it++) {
            int m = it * 16 + rb;
            int gm = m0 + m;
            const float* gr = &gsm[m * GSM_STRIDE];
            const __half* xr = &xbuf[m * XB_STRIDE];
            float2 gi = *(const float2*)&gr[hl];
            float2 gf = *(const float2*)&gr[32 + hl];
            float2 gg = *(const float2*)&gr[64 + hl];
            float2 go = *(const float2*)&gr[96 + hl];
            float2 xi  = __half22float2(*(const __half2*)&xr[hl]);
            float2 xf  = __half22float2(*(const __half2*)&xr[32 + hl]);
            float2 xgg = __half22float2(*(const __half2*)&xr[64 + hl]);
            float2 xo  = __half22float2(*(const __half2*)&xr[96 + hl]);
            int ci = dir * Bq * Hq + gm * Hq + ht0 + hl;
            float2 cprev = (step == 0) ? make_float2(0.f, 0.f) : *(const float2*)&g_c[ci];
            float2 cv, hv;
            cv.x = sig_fast(gf.x + xf.x) * cprev.x + sig_fast(gi.x + xi.x) * tanh_fast(gg.x + xgg.x);
            cv.y = sig_fast(gf.y + xf.y) * cprev.y + sig_fast(gi.y + xi.y) * tanh_fast(gg.y + xgg.y);
            hv.x = sig_fast(go.x + xo.x) * tanh_fast(cv.x);
            hv.y = sig_fast(go.y + xo.y) * tanh_fast(cv.y);
            *(float2*)&g_c[ci] = cv;
            __half2 hh = __floats2half2_rn(hv.x, hv.y);
            if (LAYER0) {
                size_t so = ((size_t)gm * Wq + t_) * (2 * Hq) + dir * Hq + ht0 + hl;
                *(__half2*)&g_hseq_h[so] = hh;
            } else {
                *(__half2*)&haw[gm * Hq + ht0 + hl] = hh;
                if (t_ == qlen[gm] - 1) {
                    *(float2*)&out[(size_t)gm * (2 * Hq) + dir * Hq + ht0 + hl] = hv;
                }
            }
        }

        // ---- arrive; fill skew window with next step's xg GEMM; then wait ----
        if (step < Wq - 1) {
            __threadfence();
            __syncthreads();      // all epilogue gsm/xbuf reads done
            unsigned* ctr = &g_gbar[bar_ofs + grp * Wq + step];
            if (tid == 0) atomicAdd(ctr, 1u);

            xg_gemm(dir ? (Wq - 2 - step) : (step + 1));

            // prefetch next step's gates weights
            load_Bw(0, 0);
            load_Bw(1, 64);

            if (tid == 0) {
                unsigned v;
                do {
                    asm volatile("ld.acquire.gpu.u32 %0, [%1];"
                                 : "=r"(v) : "l"(ctr) : "memory");
                    if (v < 16u) __nanosleep(32);
                } while (v < 16u);
            }
            __syncthreads();
        }
    }
}

// ---------------- launch ----------------
extern "C" void kernel_launch(void* const* d_in, const int* in_sizes, int n_in,
                              void* d_out, int out_size)
{
    const int*   ques = (const int*)d_in[0];
    const int*   qlen = (const int*)d_in[1];
    const float* lut  = (const float*)d_in[2];
    const float* wih0 = (const float*)d_in[3];
    const float* whh0 = (const float*)d_in[4];
    const float* b0   = (const float*)d_in[5];
    const float* wih1 = (const float*)d_in[6];
    const float* whh1 = (const float*)d_in[7];
    const float* b1   = (const float*)d_in[8];
    float* out = (float*)d_out;

    __half* wr;
    cudaGetSymbolAddress((void**)&wr, g_wr);

    cudaFuncSetAttribute(lstm_fused<0>, cudaFuncAttributeMaxDynamicSharedMemorySize, F_SMEM);
    cudaFuncSetAttribute(lstm_fused<1>, cudaFuncAttributeMaxDynamicSharedMemorySize, F_SMEM);

    // 0) fused: all weights -> half + barrier zeroing; table build
    cvt_all_weights_kernel<<<(W_TOTAL / 4 + 255) / 256, 256>>>(wih0, whh0, wih1, whh1);
    {
        dim3 grid((Vq + 31) / 32, Eq / 32);
        tanh_transpose_kernel<<<grid, dim3(32, 8)>>>(lut);
    }

    // 1) layer 0: fused projection + recurrence (emb gather inside)
    lstm_fused<1><<<R_NCTA, 256, F_SMEM>>>(wr + OFF_WHH0, wr + OFF_WIH0, b0,
                                           ques, qlen, out, 0);

    // 2) layer 1: fused projection + recurrence; writes out directly
    lstm_fused<0><<<R_NCTA, 256, F_SMEM>>>(wr + OFF_WHH1, wr + OFF_WIH1, b1,
                                           ques, qlen, out, 32 * Wq);
}

// round 17
// speedup vs baseline: 1.0244x; 1.0244x over previous
#include <cuda_runtime.h>
#include <cuda_fp16.h>
#include <math.h>
#include <stdint.h>

#define Bq 512
#define Wq 40
#define Vq 12000
#define Eq 512
#define Hq 512
#define G4 2048   // 4*H
#define R_NCTA 256

// ---------------- scratch (device globals; no allocation) ----------------
__device__ __half g_table[(size_t)Vq * Eq];       // half tanh(lut^T)
__device__ __half g_xg[2 * (size_t)Bq * Wq * G4]; // per-dir input projections (half)
__device__ __half g_hseq_h[Bq * Wq * 2 * Hq];     // layer-0 output (half; also next-A)
__device__ __half g_ha[2][2 * Bq * Hq];           // h ping-pong (layer-1 A)
__device__ float g_c[2 * Bq * Hq];
__device__ __half g_wr[10485760];                 // half weights: wih0|whh0|wih1|whh1
__device__ unsigned g_gbar[2 * 32 * Wq];          // group barriers [layer][group][step]

#define OFF_WIH0 0
#define OFF_WHH0 2097152
#define OFF_WIH1 4194304
#define OFF_WHH1 8388608
#define W_TOTAL  10485760
#define CVT_BLOCKS 10240        // W_TOTAL/4/256
#define TBL_BX 375              // (Vq+31)/32
#define TBL_BLOCKS (TBL_BX * (Eq / 32))

__device__ __forceinline__ float sig_fast(float x) {
    return __fdividef(1.0f, 1.0f + __expf(-x));
}
__device__ __forceinline__ float tanh_fast(float x) {
    return 2.0f * __fdividef(1.0f, 1.0f + __expf(-2.0f * x)) - 1.0f;
}
__device__ __forceinline__ void cp16(uint32_t dst, const void* src) {
    asm volatile("cp.async.cg.shared.global [%0], [%1], 16;" :: "r"(dst), "l"(src));
}
__device__ __forceinline__ void cp16z(uint32_t dst, const void* src, int sz) {
    asm volatile("cp.async.cg.shared.global [%0], [%1], 16, %2;"
                 :: "r"(dst), "l"(src), "r"(sz));
}
#define LDSM_X4(r0, r1, r2, r3, addr) \
    asm volatile("ldmatrix.sync.aligned.m8n8.x4.shared.b16 {%0,%1,%2,%3}, [%4];" \
                 : "=r"(r0), "=r"(r1), "=r"(r2), "=r"(r3) : "r"(addr))

// ---------------- fused prologue: weights->half, barrier zero, tanh table ------
__global__ void prologue_kernel(const float* __restrict__ w0, const float* __restrict__ w1,
                                const float* __restrict__ w2, const float* __restrict__ w3,
                                const float* __restrict__ lut) {
    __shared__ float tile[32][33];
    int bid = blockIdx.x;
    int tid = threadIdx.x;
    if (bid < CVT_BLOCKS) {
        int i = bid * 256 + tid;
        if (i < 2 * 32 * Wq) g_gbar[i] = 0;
        int idx4 = i * 4;
        if (idx4 >= W_TOTAL) return;
        const float* src; int off;
        if (idx4 < OFF_WHH0)      { src = w0; off = idx4; }
        else if (idx4 < OFF_WIH1) { src = w1; off = idx4 - OFF_WHH0; }
        else if (idx4 < OFF_WHH1) { src = w2; off = idx4 - OFF_WIH1; }
        else                      { src = w3; off = idx4 - OFF_WHH1; }
        float4 v = *(const float4*)(src + off);
        __half2 a = __floats2half2_rn(v.x, v.y);
        __half2 b = __floats2half2_rn(v.z, v.w);
        __half2* dst = (__half2*)&g_wr[idx4];
        dst[0] = a; dst[1] = b;
    } else {
        int b = bid - CVT_BLOCKS;
        int v0 = (b % TBL_BX) * 32;
        int e0 = (b / TBL_BX) * 32;
        int tx = tid & 31, ty = tid >> 5;   // 32 x 8
#pragma unroll
        for (int i = ty; i < 32; i += 8) {
            int e = e0 + i, v = v0 + tx;
            tile[i][tx] = (v < Vq) ? lut[(size_t)e * Vq + v] : 0.0f;
        }
        __syncthreads();
#pragma unroll
        for (int i = ty; i < 32; i += 8) {
            int v = v0 + i, e = e0 + tx;
            if (v < Vq) g_table[(size_t)v * Eq + e] = __float2half_rn(tanhf(tile[tx][i]));
        }
    }
}

// ---------------- FP16 tensor-core NT GEMM, 4-stage cp.async + ldmatrix --------
// EMB=1: A rows gathered from g_table via ques (v==0 -> zero row).
#define P_ASZ (128 * 20)            // u32 per stage
#define P_SMEM (4 * P_ASZ * 2 * 4)  // 81920 B
template <int HAS_BIAS, int EMB>
__global__ __launch_bounds__(256, 2) void gemm_hf(
    const __half* __restrict__ A, size_t aDirStride,
    const __half* __restrict__ Bw, size_t bDirStride,
    const float* __restrict__ bias,
    __half* __restrict__ C, size_t cDirStride,
    int M, int N, int K,
    const int* __restrict__ ques)
{
    extern __shared__ uint32_t sm[];
    uint32_t* smA = sm;                 // [4][128][20]
    uint32_t* smB = sm + 4 * P_ASZ;
    uint32_t baseA = (uint32_t)__cvta_generic_to_shared(smA);
    uint32_t baseB = (uint32_t)__cvta_generic_to_shared(smB);

    int dir = blockIdx.z;
    A  += (size_t)dir * aDirStride;
    Bw += (size_t)dir * bDirStride;
    C  += (size_t)dir * cDirStride;

    int m0 = blockIdx.y * 128;
    int n0 = blockIdx.x * 128;
    int tid = threadIdx.x;
    int wid = tid >> 5, lane = tid & 31;
    int wm = wid >> 2, wn = wid & 3;
    int gid = lane >> 2, tg = lane & 3;

    int r0 = tid >> 2;
    int seg0 = tid & 3;
    long arow0 = 0, arow1 = 0;
    int asz0 = 16, asz1 = 16;
    if (EMB) {
        int v0 = ques[m0 + r0];
        int v1 = ques[m0 + r0 + 64];
        arow0 = (long)(v0 > 0 ? v0 - 1 : 0) * Eq;
        arow1 = (long)(v1 > 0 ? v1 - 1 : 0) * Eq;
        asz0 = v0 > 0 ? 16 : 0;
        asz1 = v1 > 0 ? 16 : 0;
    }

    int lrow = (lane & 7) + ((lane >> 3) & 1) * 8;
    int lk = (lane >> 4) * 4;
    uint32_t aAddr = baseA + (uint32_t)(((wm * 64 + lrow) * 20 + lk) * 4);
    uint32_t bAddr = baseB + (uint32_t)(((wn * 32 + lrow) * 20 + lk) * 4);

    float acc[4][4][4];
#pragma unroll
    for (int mt = 0; mt < 4; mt++)
#pragma unroll
        for (int nt = 0; nt < 4; nt++)
#pragma unroll
            for (int r = 0; r < 4; r++) acc[mt][nt][r] = 0.0f;

    int niter = K >> 5;

    auto load_stage = [&](int s, int k0) {
#pragma unroll
        for (int i = 0; i < 2; i++) {
            int c = tid + i * 256;
            int row = c >> 2, seg = c & 3;
            uint32_t da = baseA + (s * P_ASZ + row * 20 + seg * 4) * 4;
            if (EMB) {
                cp16z(da, A + (i ? arow1 : arow0) + k0 + seg0 * 8, i ? asz1 : asz0);
            } else {
                cp16(da, A + (size_t)(m0 + row) * K + k0 + seg * 8);
            }
            cp16(baseB + (s * P_ASZ + row * 20 + seg * 4) * 4,
                 Bw + (size_t)(n0 + row) * K + k0 + seg * 8);
        }
        asm volatile("cp.async.commit_group;");
    };

    load_stage(0, 0);
    load_stage(1, 32);
    load_stage(2, 64);

    for (int it = 0; it < niter; it++) {
        int rem = niter - 1 - it;
        if (rem >= 2)      asm volatile("cp.async.wait_group 2;");
        else if (rem == 1) asm volatile("cp.async.wait_group 1;");
        else               asm volatile("cp.async.wait_group 0;");
        __syncthreads();
        if (it + 3 < niter) load_stage((it + 3) & 3, (it + 3) * 32);

        uint32_t sofs = (uint32_t)((it & 3) * P_ASZ * 4);
#pragma unroll
        for (int g = 0; g < 2; g++) {
            uint32_t kby = g * 32;
            uint32_t af[4][4], bf[4][2];
#pragma unroll
            for (int mt = 0; mt < 4; mt++)
                LDSM_X4(af[mt][0], af[mt][1], af[mt][2], af[mt][3],
                        aAddr + sofs + (uint32_t)(mt * 16 * 20 * 4) + kby);
#pragma unroll
            for (int p = 0; p < 2; p++)
                LDSM_X4(bf[2 * p][0], bf[2 * p + 1][0], bf[2 * p][1], bf[2 * p + 1][1],
                        bAddr + sofs + (uint32_t)(p * 16 * 20 * 4) + kby);
#pragma unroll
            for (int mt = 0; mt < 4; mt++)
#pragma unroll
                for (int nt = 0; nt < 4; nt++) {
                    asm volatile(
                        "mma.sync.aligned.m16n8k16.row.col.f32.f16.f16.f32 "
                        "{%0,%1,%2,%3}, {%4,%5,%6,%7}, {%8,%9}, {%0,%1,%2,%3};"
                        : "+f"(acc[mt][nt][0]), "+f"(acc[mt][nt][1]),
                          "+f"(acc[mt][nt][2]), "+f"(acc[mt][nt][3])
                        : "r"(af[mt][0]), "r"(af[mt][1]), "r"(af[mt][2]), "r"(af[mt][3]),
                          "r"(bf[nt][0]), "r"(bf[nt][1]));
                }
        }
    }

    const float* bp = bias + (size_t)dir * 2 * G4;
#pragma unroll
    for (int mt = 0; mt < 4; mt++) {
#pragma unroll
        for (int nt = 0; nt < 4; nt++) {
            int m = m0 + wm * 64 + mt * 16 + gid;
            int n = n0 + wn * 32 + nt * 8 + tg * 2;
            float2 v0, v1;
            v0.x = acc[mt][nt][0]; v0.y = acc[mt][nt][1];
            v1.x = acc[mt][nt][2]; v1.y = acc[mt][nt][3];
            if (HAS_BIAS) {
                float bx = bp[n] + bp[G4 + n];
                float by = bp[n + 1] + bp[G4 + n + 1];
                v0.x += bx; v0.y += by; v1.x += bx; v1.y += by;
            }
            *(__half2*)(C + (size_t)m * N + n) = __floats2half2_rn(v0.x, v0.y);
            *(__half2*)(C + (size_t)(m + 8) * N + n) = __floats2half2_rn(v1.x, v1.y);
        }
    }
}

// ---------------- persistent fused LSTM recurrence, 256 CTAs / 2 per SM --------
// Release/acquire barrier (no full threadfence); qlen hoisted (LAYER0=0).
#define R2_ASZ (64 * 36)        // u32
#define R2_BSZ (128 * 36)       // u32
#define R2_A0  (2 * R2_BSZ)
#define R2_B2  (2 * R2_BSZ + 3 * R2_ASZ)
#define R2_SMEM ((3 * R2_BSZ + 3 * R2_ASZ) * 4)   // 82944 B
#define GSM_STRIDE 130
template <int LAYER0>
__global__ __launch_bounds__(256, 2) void lstm_persist(
    const __half* __restrict__ whh,      // [2 dirs][G4][Hq] half
    const __half* __restrict__ xg,       // [2 dirs][Bq][Wq][G4] half
    const int* __restrict__ qlen,
    float* __restrict__ out,
    int bar_ofs)
{
    extern __shared__ uint32_t sm[];
    float* gsm = (float*)(sm + R2_A0);    // [64][130] aliases A0..B2
    uint32_t base = (uint32_t)__cvta_generic_to_shared(sm);

    int tid = threadIdx.x;
    int bx = blockIdx.x;
    int dir = bx >> 7;
    int r = bx & 127;
    int m0 = (r >> 4) * 64;
    int ht0 = (r & 15) * 32;
    int grp = bx >> 4;

    int wid = tid >> 5, lane = tid & 31;
    int wm = wid >> 2, wn = wid & 3;
    int gid = lane >> 2, tg = lane & 3;

    int lrow = (lane & 7) + ((lane >> 3) & 1) * 8;
    int lk = (lane >> 4) * 4;
    uint32_t aLane = base + (uint32_t)(((wm * 32 + lrow) * 36 + lk) * 4);
    uint32_t bLane = base + (uint32_t)(((wn * 32 + lrow) * 36 + lk) * 4);

    const __half* wbase = whh + (size_t)dir * G4 * Hq;
    const __half* xgd = xg + (size_t)dir * Bq * Wq * G4;

    // hoisted qlen targets (LAYER0=0 epilogue)
    int qv[4];
    if (!LAYER0) {
#pragma unroll
        for (int it = 0; it < 4; it++)
            qv[it] = qlen[m0 + it * 16 + (tid >> 4)] - 1;
    }

    auto aStage = [&](int s) -> uint32_t { return (uint32_t)((R2_A0 + s * R2_ASZ) * 4); };
    auto bStage = [&](int s) -> uint32_t {
        return (uint32_t)((s == 2 ? R2_B2 : s * R2_BSZ) * 4);
    };

    const __half* habase = nullptr;
    size_t rstride = LAYER0 ? (size_t)Wq * 2 * Hq : (size_t)Hq;

    auto load_A = [&](int s, int k0) {
        uint32_t ab = base + aStage(s);
#pragma unroll
        for (int i = 0; i < 2; i++) {
            int c = tid + i * 256;
            int row = c >> 3, seg = c & 7;
            cp16(ab + (uint32_t)((row * 36 + seg * 4) * 4),
                 habase + (size_t)(m0 + row) * rstride + k0 + seg * 8);
        }
        asm volatile("cp.async.commit_group;");
    };
    auto load_Bw = [&](int s, int k0) {
        uint32_t bb = base + bStage(s);
#pragma unroll
        for (int i = 0; i < 4; i++) {
            int c = tid + i * 256;
            int row = c >> 3, seg = c & 7;
            int grow = ((row >> 5) << 9) + ht0 + (row & 31);
            cp16(bb + (uint32_t)((row * 36 + seg * 4) * 4),
                 wbase + (size_t)grow * Hq + k0 + seg * 8);
        }
        asm volatile("cp.async.commit_group;");
    };
    auto load_AB = [&](int s, int k0) {
        uint32_t ab = base + aStage(s);
        uint32_t bb = base + bStage(s);
#pragma unroll
        for (int i = 0; i < 2; i++) {
            int c = tid + i * 256;
            int row = c >> 3, seg = c & 7;
            cp16(ab + (uint32_t)((row * 36 + seg * 4) * 4),
                 habase + (size_t)(m0 + row) * rstride + k0 + seg * 8);
        }
#pragma unroll
        for (int i = 0; i < 4; i++) {
            int c = tid + i * 256;
            int row = c >> 3, seg = c & 7;
            int grow = ((row >> 5) << 9) + ht0 + (row & 31);
            cp16(bb + (uint32_t)((row * 36 + seg * 4) * 4),
                 wbase + (size_t)grow * Hq + k0 + seg * 8);
        }
        asm volatile("cp.async.commit_group;");
    };

    for (int step = 0; step < Wq; step++) {
        int t_ = dir ? (Wq - 1 - step) : step;

        // L2-prefetch this step's xg slice
        if (tid < 256) {
            int row = tid >> 2, seg = tid & 3;
            const __half* p = xgd + ((size_t)(m0 + row) * Wq + t_) * G4
                              + seg * 512 + ht0;
            asm volatile("prefetch.global.L2 [%0];" :: "l"(p));
        }

        float acc[2][4][4];
#pragma unroll
        for (int mt = 0; mt < 2; mt++)
#pragma unroll
            for (int nt = 0; nt < 4; nt++)
#pragma unroll
                for (int q = 0; q < 4; q++) acc[mt][nt][q] = 0.0f;

        if (step > 0) {
            if (LAYER0) {
                int tprev = dir ? (Wq - step) : (step - 1);
                habase = g_hseq_h + (size_t)tprev * 2 * Hq + dir * Hq;
            } else {
                habase = g_ha[(step - 1) & 1] + dir * Bq * Hq;
            }
            load_A(0, 0);
            load_A(1, 64);

            for (int kc = 0; kc < 8; kc++) {
                if (kc < 7) asm volatile("cp.async.wait_group 1;");
                else        asm volatile("cp.async.wait_group 0;");
                __syncthreads();
                if (kc == 0)      load_AB(2, 128);
                else if (kc <= 5) load_AB((kc + 2) % 3, (kc + 2) * 64);

                uint32_t sa = aStage(kc % 3);
                uint32_t sb = bStage(kc % 3);
#pragma unroll
                for (int g = 0; g < 4; g++) {
                    uint32_t kby = g * 32;
                    uint32_t af[2][4], bf[4][2];
#pragma unroll
                    for (int mt = 0; mt < 2; mt++)
                        LDSM_X4(af[mt][0], af[mt][1], af[mt][2], af[mt][3],
                                aLane + sa + (uint32_t)(mt * 16 * 36 * 4) + kby);
#pragma unroll
                    for (int p = 0; p < 2; p++)
                        LDSM_X4(bf[2 * p][0], bf[2 * p + 1][0], bf[2 * p][1], bf[2 * p + 1][1],
                                bLane + sb + (uint32_t)(p * 16 * 36 * 4) + kby);
#pragma unroll
                    for (int mt = 0; mt < 2; mt++)
#pragma unroll
                        for (int nt = 0; nt < 4; nt++) {
                            asm volatile(
                                "mma.sync.aligned.m16n8k16.row.col.f32.f16.f16.f32 "
                                "{%0,%1,%2,%3}, {%4,%5,%6,%7}, {%8,%9}, {%0,%1,%2,%3};"
                                : "+f"(acc[mt][nt][0]), "+f"(acc[mt][nt][1]),
                                  "+f"(acc[mt][nt][2]), "+f"(acc[mt][nt][3])
                                : "r"(af[mt][0]), "r"(af[mt][1]), "r"(af[mt][2]), "r"(af[mt][3]),
                                  "r"(bf[nt][0]), "r"(bf[nt][1]));
                        }
                }
            }
        }

        __syncthreads();
        if (step < Wq - 1) {
            load_Bw(0, 0);
            load_Bw(1, 64);
        }

        // ---- stage gates into gsm ----
#pragma unroll
        for (int mt = 0; mt < 2; mt++)
#pragma unroll
            for (int nt = 0; nt < 4; nt++)
#pragma unroll
                for (int rs = 0; rs < 2; rs++) {
                    int mr = wm * 32 + mt * 16 + gid + rs * 8;
                    int nc = wn * 32 + nt * 8 + tg * 2;
                    float2 v;
                    v.x = acc[mt][nt][rs * 2];
                    v.y = acc[mt][nt][rs * 2 + 1];
                    *(float2*)&gsm[mr * GSM_STRIDE + nc] = v;
                }
        __syncthreads();

        // ---- coalesced fused gate epilogue ----
        __half* haw = LAYER0 ? nullptr : (g_ha[step & 1] + dir * Bq * Hq);
        int hl = (tid & 15) * 2;
        int rb = tid >> 4;
#pragma unroll
        for (int it = 0; it < 4; it++) {
            int m = it * 16 + rb;
            int gm = m0 + m;
            const float* gr = &gsm[m * GSM_STRIDE];
            const __half* xp = xgd + ((size_t)gm * Wq + t_) * G4 + ht0 + hl;
            float2 gi = *(const float2*)&gr[hl];
            float2 gf = *(const float2*)&gr[32 + hl];
            float2 gg = *(const float2*)&gr[64 + hl];
            float2 go = *(const float2*)&gr[96 + hl];
            float2 xi  = __half22float2(*(const __half2*)&xp[0]);
            float2 xf  = __half22float2(*(const __half2*)&xp[512]);
            float2 xgg = __half22float2(*(const __half2*)&xp[1024]);
            float2 xo  = __half22float2(*(const __half2*)&xp[1536]);
            int ci = dir * Bq * Hq + gm * Hq + ht0 + hl;
            float2 cprev = (step == 0) ? make_float2(0.f, 0.f) : *(const float2*)&g_c[ci];
            float2 cv, hv;
            cv.x = sig_fast(gf.x + xf.x) * cprev.x + sig_fast(gi.x + xi.x) * tanh_fast(gg.x + xgg.x);
            cv.y = sig_fast(gf.y + xf.y) * cprev.y + sig_fast(gi.y + xi.y) * tanh_fast(gg.y + xgg.y);
            hv.x = sig_fast(go.x + xo.x) * tanh_fast(cv.x);
            hv.y = sig_fast(go.y + xo.y) * tanh_fast(cv.y);
            *(float2*)&g_c[ci] = cv;
            __half2 hh = __floats2half2_rn(hv.x, hv.y);
            if (LAYER0) {
                size_t so = ((size_t)gm * Wq + t_) * (2 * Hq) + dir * Hq + ht0 + hl;
                *(__half2*)&g_hseq_h[so] = hh;
            } else {
                *(__half2*)&haw[gm * Hq + ht0 + hl] = hh;
                if (t_ == qv[it]) {
                    *(float2*)&out[(size_t)gm * (2 * Hq) + dir * Hq + ht0 + hl] = hv;
                }
            }
        }

        // ---- group-local barrier: release arrive + acquire spin ----
        if (step < Wq - 1) {
            __syncthreads();
            if (tid == 0) {
                unsigned* ctr = &g_gbar[bar_ofs + grp * Wq + step];
                unsigned old;
                asm volatile("atom.release.gpu.global.add.u32 %0, [%1], %2;"
                             : "=r"(old) : "l"(ctr), "r"(1u) : "memory");
                unsigned v;
                do {
                    asm volatile("ld.acquire.gpu.u32 %0, [%1];"
                                 : "=r"(v) : "l"(ctr) : "memory");
                    if (v < 16u) __nanosleep(32);
                } while (v < 16u);
            }
            __syncthreads();
        }
    }
}

// ---------------- launch ----------------
extern "C" void kernel_launch(void* const* d_in, const int* in_sizes, int n_in,
                              void* d_out, int out_size)
{
    const int*   ques = (const int*)d_in[0];
    const int*   qlen = (const int*)d_in[1];
    const float* lut  = (const float*)d_in[2];
    const float* wih0 = (const float*)d_in[3];
    const float* whh0 = (const float*)d_in[4];
    const float* b0   = (const float*)d_in[5];
    const float* wih1 = (const float*)d_in[6];
    const float* whh1 = (const float*)d_in[7];
    const float* b1   = (const float*)d_in[8];
    float* out = (float*)d_out;

    __half *table, *hseq_h, *wr, *xg;
    cudaGetSymbolAddress((void**)&table,  g_table);
    cudaGetSymbolAddress((void**)&xg,     g_xg);
    cudaGetSymbolAddress((void**)&hseq_h, g_hseq_h);
    cudaGetSymbolAddress((void**)&wr,     g_wr);

    cudaFuncSetAttribute(gemm_hf<1, 1>, cudaFuncAttributeMaxDynamicSharedMemorySize, P_SMEM);
    cudaFuncSetAttribute(gemm_hf<1, 0>, cudaFuncAttributeMaxDynamicSharedMemorySize, P_SMEM);
    cudaFuncSetAttribute(lstm_persist<0>, cudaFuncAttributeMaxDynamicSharedMemorySize, R2_SMEM);
    cudaFuncSetAttribute(lstm_persist<1>, cudaFuncAttributeMaxDynamicSharedMemorySize, R2_SMEM);

    // 0) fused prologue: weights->half + barrier zero + tanh table
    prologue_kernel<<<CVT_BLOCKS + TBL_BLOCKS, 256>>>(wih0, whh0, wih1, whh1, lut);

    // 1) layer-0 input projection (embedding gather fused into A-load)
    {
        dim3 grid(G4 / 128, (Bq * Wq) / 128, 2);
        gemm_hf<1, 1><<<grid, 256, P_SMEM>>>(table, 0,
                                             wr + OFF_WIH0, (size_t)G4 * Eq,
                                             b0,
                                             xg, (size_t)Bq * Wq * G4,
                                             Bq * Wq, G4, Eq, ques);
    }

    // 2) layer-0 recurrence
    lstm_persist<1><<<R_NCTA, 256, R2_SMEM>>>(wr + OFF_WHH0, xg, qlen, out, 0);

    // 3) layer-1 input projection (K = 2H, A = half hseq)
    {
        dim3 grid(G4 / 128, (Bq * Wq) / 128, 2);
        gemm_hf<1, 0><<<grid, 256, P_SMEM>>>(hseq_h, 0,
                                             wr + OFF_WIH1, (size_t)G4 * 2 * Hq,
                                             b1,
                                             xg, (size_t)Bq * Wq * G4,
                                             Bq * Wq, G4, 2 * Hq, ques);
    }

    // 4) layer-1 recurrence (writes out directly at t = qlen-1)
    lstm_persist<0><<<R_NCTA, 256, R2_SMEM>>>(wr + OFF_WHH1, xg, qlen, out, 32 * Wq);
}